// round 3
// baseline (speedup 1.0000x reference)
#include <cuda_runtime.h>
#include <cuda_bf16.h>
#include <cstdint>

// Shapes (fixed by the problem):
//   x:     [4, 256, 64, 64]
//   h:     [4, 128, 64, 64]   (half-res; h_up = 2x nearest upsample of h)
//   wgt:   [4, 200, 64, 64]   (kernel-gen branch, computed at HALF res:
//                              it is constant over each 2x2 upsampled block)
//   out:   [4, 128, 128, 128]
#define B_     4
#define CIN    256
#define COUT   128
#define HHALF  64
#define PHALF  4096        // 64*64
#define CRED   32
#define GROUPS 8
#define GC_    16
#define KK     25          // 5x5
#define SPAN   200         // KK*GROUPS

// Scratch (device globals; allocation inside kernel_launch is forbidden)
__device__ float g_h  [(size_t)B_ * COUT * PHALF];   // 8.4 MB
__device__ float g_wgt[(size_t)B_ * SPAN * PHALF];   // 13.1 MB

// ---------------------------------------------------------------------------
// Kernel 1: h = conv1x1(x, w1x1) + b1x1      (per-b GEMM [128x256]@[256x4096])
// Tile: M=128 (all out channels), N=128 pixels, Kc=16. 8x8 microtile/thread.
// ---------------------------------------------------------------------------
__global__ __launch_bounds__(256) void conv1_k(const float* __restrict__ x,
                                               const float* __restrict__ w,
                                               const float* __restrict__ bias) {
    __shared__ float ws[16][129];   // [k][o], padded
    __shared__ float xs[16][132];   // [k][p], padded

    const int b  = blockIdx.z;
    const int p0 = blockIdx.x * 128;
    const int tid = threadIdx.x;
    const int tx = tid & 15, ty = tid >> 4;

    float acc[8][8];
#pragma unroll
    for (int i = 0; i < 8; i++)
#pragma unroll
        for (int j = 0; j < 8; j++) acc[i][j] = 0.f;

    const float* xb = x + (size_t)b * CIN * PHALF + p0;

    for (int kc = 0; kc < CIN; kc += 16) {
        // load X tile: 16 k-rows x 128 pixels (coalesced)
#pragma unroll
        for (int i = 0; i < 8; i++) {
            int e = tid + i * 256;
            int kk = e >> 7, pp = e & 127;
            xs[kk][pp] = xb[(size_t)(kc + kk) * PHALF + pp];
        }
        // load W tile: w[o*CIN + kc+kk]; lanes read 16 consecutive k
#pragma unroll
        for (int i = 0; i < 8; i++) {
            int e = tid + i * 256;
            int kk = e & 15, oo = e >> 4;
            ws[kk][oo] = w[oo * CIN + kc + kk];
        }
        __syncthreads();
#pragma unroll
        for (int k = 0; k < 16; k++) {
            float wr[8], xr[8];
#pragma unroll
            for (int i = 0; i < 8; i++) wr[i] = ws[k][ty + 16 * i];
#pragma unroll
            for (int j = 0; j < 8; j++) xr[j] = xs[k][tx + 16 * j];
#pragma unroll
            for (int i = 0; i < 8; i++)
#pragma unroll
                for (int j = 0; j < 8; j++) acc[i][j] += wr[i] * xr[j];
        }
        __syncthreads();
    }
#pragma unroll
    for (int i = 0; i < 8; i++) {
        int o = ty + 16 * i;
        float bv = bias[o];
#pragma unroll
        for (int j = 0; j < 8; j++) {
            int p = p0 + tx + 16 * j;
            g_h[((size_t)b * COUT + o) * PHALF + p] = acc[i][j] + bv;
        }
    }
}

// ---------------------------------------------------------------------------
// Kernel 2: kernel-generation branch AT HALF RES.
//   r   = relu(bn(w_red @ h + b_red))         [4, 32, 64, 64]
//   wgt = w_span @ r + b_span                 [4, 200, 64, 64]
// Block = 128 pixels, 256 threads. r staged in shared between the two GEMMs.
// Shared pool reused: stage1 {wred^T 16KB + h-chunk 8KB}, stage2 {wspan 25.6KB}.
// ---------------------------------------------------------------------------
__global__ __launch_bounds__(256) void kgen_k(const float* __restrict__ wred,
                                              const float* __restrict__ bred,
                                              const float* __restrict__ gamma,
                                              const float* __restrict__ beta,
                                              const float* __restrict__ mean,
                                              const float* __restrict__ var,
                                              const float* __restrict__ wspan,
                                              const float* __restrict__ bspan) {
    __shared__ float pool[6400];        // stage1: wred^T[4096] + h_sh[2048]; stage2: wspan[6400]
    __shared__ float r_sh[CRED][129];   // [o][p] padded

    const int tid = threadIdx.x;
    const int q0  = blockIdx.x * 128;   // global half-pixel id (b*4096 + p)
    const int b   = q0 >> 12;
    const int p0  = q0 & 4095;

    // Load wred transposed into pool[0..4096): pool[c*32 + o] = wred[o*128 + c]
    for (int i = tid; i < CRED * COUT; i += 256) {
        int o = i >> 7, c = i & 127;
        pool[c * CRED + o] = wred[i];
    }

    const int o  = tid & 31;     // r-channel this thread owns
    const int pg = tid >> 5;     // pixel slice (16 pixels)

    float racc[16];
    {
        float bv = bred[o];
#pragma unroll
        for (int pp = 0; pp < 16; pp++) racc[pp] = bv;
    }

    const float* hb = g_h + (size_t)b * COUT * PHALF + p0;
    float* h_sh = pool + 4096;   // [16][128]

    for (int cc = 0; cc < COUT; cc += 16) {
        __syncthreads();
        // load 16-channel x 128-pixel chunk of h (coalesced)
        for (int i = tid; i < 16 * 128; i += 256) {
            int c = i >> 7, p = i & 127;
            h_sh[c * 128 + p] = hb[(size_t)(cc + c) * PHALF + p];
        }
        __syncthreads();
#pragma unroll
        for (int c = 0; c < 16; c++) {
            float wv = pool[(cc + c) * CRED + o];
#pragma unroll
            for (int pp = 0; pp < 16; pp++)
                racc[pp] += wv * h_sh[c * 128 + pg * 16 + pp];
        }
    }

    // BN + ReLU -> r_sh
    {
        float sc = gamma[o] * rsqrtf(var[o] + 1e-5f);
        float sh = beta[o] - mean[o] * sc;
#pragma unroll
        for (int pp = 0; pp < 16; pp++) {
            float v = racc[pp] * sc + sh;
            r_sh[o][pg * 16 + pp] = fmaxf(v, 0.f);
        }
    }
    __syncthreads();

    // stage 2: load wspan into pool (overwrites stage-1 data)
    for (int i = tid; i < SPAN * CRED; i += 256) pool[i] = wspan[i];
    __syncthreads();

    float* wb = g_wgt + (size_t)b * SPAN * PHALF + p0;
    for (int idx = tid; idx < SPAN * 128; idx += 256) {
        int s = idx >> 7, p = idx & 127;    // s uniform within a warp
        float v = bspan[s];
#pragma unroll
        for (int oo = 0; oo < CRED; oo++)
            v += pool[s * CRED + oo] * r_sh[oo][p];
        wb[(size_t)s * PHALF + p] = v;
    }
}

// ---------------------------------------------------------------------------
// Kernel 3: involution at full res.
// out[b, g*16+c, y, x] = sum_{kh,kw} wgt[b, g*25+kh*5+kw, y/2, x/2]
//                                    * h[b, g*16+c, (y+kh-2)/2, (x+kw-2)/2]
// (zero outside full-res [0,128); padding maps exactly to half-res [-1,64])
// Block: (b, g, 16x16 half-pixel tile). Thread = one half-pixel -> 2x2 outputs
// for all 16 group channels. 3x3 half-res neighborhood per channel.
// ---------------------------------------------------------------------------
__global__ __launch_bounds__(256) void inv_k(float* __restrict__ out) {
    __shared__ float hs[GC_][18][19];   // halo'd h tile, ~21.4 KB

    const int b = blockIdx.z;
    const int g = blockIdx.y;
    const int ti = (blockIdx.x >> 2) * 16;
    const int tj = (blockIdx.x & 3) * 16;
    const int tid = threadIdx.x;

    // load h tile (+1 halo each side) with zero pad
    const float* hb = g_h + ((size_t)b * COUT + g * GC_) * PHALF;
    for (int e = tid; e < GC_ * 18 * 18; e += 256) {
        int c   = e / 324;
        int rem = e - c * 324;
        int rr  = rem / 18, cc = rem - rr * 18;
        int gi = ti - 1 + rr, gj = tj - 1 + cc;
        float v = 0.f;
        if ((unsigned)gi < 64u && (unsigned)gj < 64u)
            v = hb[(size_t)c * PHALF + gi * HHALF + gj];
        hs[c][rr][cc] = v;
    }

    const int jl = tid & 15, il = tid >> 4;
    const int pix = (ti + il) * HHALF + (tj + jl);

    // 25 involution weights for this half-pixel (coalesced loads)
    float wk[KK];
    const float* wgp = g_wgt + ((size_t)b * SPAN + g * KK) * PHALF + pix;
#pragma unroll
    for (int k = 0; k < KK; k++) wk[k] = wgp[(size_t)k * PHALF];

    __syncthreads();

    // half-res row/col offset tables: index into 3x3 neighborhood (0..2)
    // di=0: floor((2i+kh-2)/2)-(i-1) ; di=1: floor((2i+1+kh-2)/2)-(i-1)
    const int R0[5] = {0, 0, 1, 1, 2};
    const int R1[5] = {0, 1, 1, 2, 2};

    const int y0 = 2 * (ti + il), x0 = 2 * (tj + jl);
    float* ob = out + (((size_t)b * COUT + g * GC_) * 128 + y0) * 128 + x0;

#pragma unroll
    for (int c = 0; c < GC_; c++) {
        float n[3][3];
#pragma unroll
        for (int a = 0; a < 3; a++)
#pragma unroll
            for (int d = 0; d < 3; d++)
                n[a][d] = hs[c][il + a][jl + d];

        float a00 = 0.f, a01 = 0.f, a10 = 0.f, a11 = 0.f;
#pragma unroll
        for (int kh = 0; kh < 5; kh++) {
            const int r0 = R0[kh], r1 = R1[kh];
#pragma unroll
            for (int kw = 0; kw < 5; kw++) {
                const float wv = wk[kh * 5 + kw];
                const int c0 = R0[kw], c1 = R1[kw];
                a00 += wv * n[r0][c0];
                a01 += wv * n[r0][c1];
                a10 += wv * n[r1][c0];
                a11 += wv * n[r1][c1];
            }
        }
        float2 v0 = make_float2(a00, a01);
        float2 v1 = make_float2(a10, a11);
        *reinterpret_cast<float2*>(ob + (size_t)c * 16384)       = v0;
        *reinterpret_cast<float2*>(ob + (size_t)c * 16384 + 128) = v1;
    }
}

// ---------------------------------------------------------------------------
extern "C" void kernel_launch(void* const* d_in, const int* in_sizes, int n_in,
                              void* d_out, int out_size) {
    const float* x      = (const float*)d_in[0];
    const float* w1x1   = (const float*)d_in[1];
    const float* b1x1   = (const float*)d_in[2];
    const float* w_red  = (const float*)d_in[3];
    const float* b_red  = (const float*)d_in[4];
    const float* gamma  = (const float*)d_in[5];
    const float* beta   = (const float*)d_in[6];
    const float* mean   = (const float*)d_in[7];
    const float* var    = (const float*)d_in[8];
    const float* w_span = (const float*)d_in[9];
    const float* b_span = (const float*)d_in[10];
    float* out = (float*)d_out;

    conv1_k<<<dim3(PHALF / 128, 1, B_), 256>>>(x, w1x1, b1x1);
    kgen_k<<<dim3((B_ * PHALF) / 128, 1, 1), 256>>>(w_red, b_red, gamma, beta,
                                                    mean, var, w_span, b_span);
    inv_k<<<dim3(16, GROUPS, B_), 256>>>(out);
}

// round 5
// speedup vs baseline: 1.1912x; 1.1912x over previous
#include <cuda_runtime.h>
#include <cuda_bf16.h>
#include <cstdint>

// Shapes (fixed by the problem):
//   x:     [4, 256, 64, 64]
//   h:     [4, 128, 64, 64]   (half-res; h_up = 2x nearest upsample of h)
//   wgt:   [4, 200, 64, 64]   (kernel-gen branch at HALF res: constant over 2x2)
//   out:   [4, 128, 128, 128]
#define B_     4
#define CIN    256
#define COUT   128
#define HHALF  64
#define PHALF  4096        // 64*64
#define CRED   32
#define GROUPS 8
#define GC_    16
#define KK     25          // 5x5
#define SPAN   200         // KK*GROUPS

// Scratch (device globals; allocation inside kernel_launch is forbidden)
__device__ float g_h  [(size_t)B_ * COUT * PHALF];   // 8.4 MB
__device__ float g_wgt[(size_t)B_ * SPAN * PHALF];   // 13.1 MB

// ---------------------------------------------------------------------------
// Kernel 1: h = conv1x1(x, w1x1) + b1x1      (per-b GEMM [128x256]@[256x4096])
// Tile: BM=64 out-channels, BN=128 pixels, BK=16. 256 threads, 4x8 microtile.
// Grid = 32 pixel-tiles x 2 o-tiles x 4 batches = 256 blocks.
// Double-buffered smem, register prefetch, 1 __syncthreads per K-step.
// ---------------------------------------------------------------------------
__global__ __launch_bounds__(256) void conv1_k(const float* __restrict__ x,
                                               const float* __restrict__ w,
                                               const float* __restrict__ bias) {
    __shared__ float xs[2][16][128];   // [buf][k][pixel]
    __shared__ float ws[2][16][68];    // [buf][k][o], stride 68 keeps rows 16B-aligned

    const int b      = blockIdx.z;
    const int o_base = blockIdx.y * 64;
    const int p0     = blockIdx.x * 128;
    const int tid = threadIdx.x;
    const int tx  = tid & 15;          // pixel lane
    const int ty  = tid >> 4;          // o lane

    const float* xb = x + (size_t)b * CIN * PHALF + p0;

    // w-tile loader indices: one float4 of 4 consecutive k per (o, quad)
    const int wq = tid & 3;            // k-quad
    const int wo = tid >> 2;           // local o (0..63)

    float acc[4][8];
#pragma unroll
    for (int i = 0; i < 4; i++)
#pragma unroll
        for (int j = 0; j < 8; j++) acc[i][j] = 0.f;

    // ---- preload tile 0 directly into smem[0] ----
    {
#pragma unroll
        for (int q = 0; q < 2; q++) {
            int f = tid + 256 * q;
            int k = f >> 5, pp4 = f & 31;
            float4 v = ((const float4*)(xb + (size_t)k * PHALF))[pp4];
            ((float4*)&xs[0][k][0])[pp4] = v;
        }
        float4 wv = *(const float4*)(w + (size_t)(o_base + wo) * CIN + 4 * wq);
        ws[0][4 * wq + 0][wo] = wv.x;
        ws[0][4 * wq + 1][wo] = wv.y;
        ws[0][4 * wq + 2][wo] = wv.z;
        ws[0][4 * wq + 3][wo] = wv.w;
    }
    __syncthreads();

    for (int it = 0; it < 16; ++it) {
        const int cur = it & 1;
        const int kc_next = (it + 1) * 16;

        // prefetch next tile into registers (no smem touch yet)
        float4 xr[2], wr;
        if (it < 15) {
#pragma unroll
            for (int q = 0; q < 2; q++) {
                int f = tid + 256 * q;
                int k = f >> 5, pp4 = f & 31;
                xr[q] = ((const float4*)(xb + (size_t)(kc_next + k) * PHALF))[pp4];
            }
            wr = *(const float4*)(w + (size_t)(o_base + wo) * CIN + kc_next + 4 * wq);
        }

        // compute on current buffer
#pragma unroll
        for (int k = 0; k < 16; k++) {
            float4 wv = *(const float4*)&ws[cur][k][4 * ty];
            float2 xv[4];
#pragma unroll
            for (int g = 0; g < 4; g++)
                xv[g] = *(const float2*)&xs[cur][k][2 * tx + 32 * g];

            float wa0 = wv.x, wa1 = wv.y, wa2 = wv.z, wa3 = wv.w;
#pragma unroll
            for (int g = 0; g < 4; g++) {
                acc[0][2*g]   += wa0 * xv[g].x;  acc[0][2*g+1] += wa0 * xv[g].y;
                acc[1][2*g]   += wa1 * xv[g].x;  acc[1][2*g+1] += wa1 * xv[g].y;
                acc[2][2*g]   += wa2 * xv[g].x;  acc[2][2*g+1] += wa2 * xv[g].y;
                acc[3][2*g]   += wa3 * xv[g].x;  acc[3][2*g+1] += wa3 * xv[g].y;
            }
        }

        // commit prefetched tile to the other buffer
        if (it < 15) {
            const int nxt = cur ^ 1;
#pragma unroll
            for (int q = 0; q < 2; q++) {
                int f = tid + 256 * q;
                int k = f >> 5, pp4 = f & 31;
                ((float4*)&xs[nxt][k][0])[pp4] = xr[q];
            }
            ws[nxt][4 * wq + 0][wo] = wr.x;
            ws[nxt][4 * wq + 1][wo] = wr.y;
            ws[nxt][4 * wq + 2][wo] = wr.z;
            ws[nxt][4 * wq + 3][wo] = wr.w;
        }
        __syncthreads();
    }

    // epilogue: bias + store (float2, coalesced)
#pragma unroll
    for (int ii = 0; ii < 4; ii++) {
        int o = o_base + 4 * ty + ii;
        float bv = bias[o];
        float* op = g_h + ((size_t)b * COUT + o) * PHALF + p0;
#pragma unroll
        for (int g = 0; g < 4; g++) {
            float2 v = make_float2(acc[ii][2*g] + bv, acc[ii][2*g+1] + bv);
            *(float2*)(op + 2 * tx + 32 * g) = v;
        }
    }
}

// ---------------------------------------------------------------------------
// Kernel 2: kernel-generation branch AT HALF RES.
//   r   = relu(bn(w_red @ h + b_red))         [4, 32, 64, 64]
//   wgt = w_span @ r + b_span                 [4, 200, 64, 64]
// Block = 64 pixels, 256 threads -> grid 256.
// Stage 2: each thread computes 4 span rows (s, s+50, s+100, s+150) sharing
// one r_sh read -> 128 FMA per 32 LDS.
// ---------------------------------------------------------------------------
__global__ __launch_bounds__(256) void kgen_k(const float* __restrict__ wred,
                                              const float* __restrict__ bred,
                                              const float* __restrict__ gamma,
                                              const float* __restrict__ beta,
                                              const float* __restrict__ mean,
                                              const float* __restrict__ var,
                                              const float* __restrict__ wspan,
                                              const float* __restrict__ bspan) {
    __shared__ float pool[6400];        // stage1: wredT[4096] + h_sh[1024]; stage2: wspan[6400]
    __shared__ float r_sh[CRED][65];    // [o][p] padded

    const int tid = threadIdx.x;
    const int q0  = blockIdx.x * 64;    // global half-pixel id (b*4096 + p)
    const int b   = q0 >> 12;
    const int p0  = q0 & 4095;

    // wred transposed: pool[c*32 + o] = wred[o*128 + c]
    for (int i = tid; i < CRED * COUT; i += 256) {
        int o = i >> 7, c = i & 127;
        pool[c * CRED + o] = wred[i];
    }

    const int o  = tid & 31;      // r-channel this thread owns
    const int pg = tid >> 5;      // pixel slice (8 pixels)

    float racc[8];
    {
        float bv = bred[o];
#pragma unroll
        for (int pp = 0; pp < 8; pp++) racc[pp] = bv;
    }

    const float* hb = g_h + (size_t)b * COUT * PHALF + p0;
    float* h_sh = pool + 4096;    // [16][64]

    for (int cc = 0; cc < COUT; cc += 16) {
        __syncthreads();
        for (int i = tid; i < 16 * 64; i += 256) {
            int c = i >> 6, p = i & 63;
            h_sh[c * 64 + p] = hb[(size_t)(cc + c) * PHALF + p];
        }
        __syncthreads();
#pragma unroll
        for (int c = 0; c < 16; c++) {
            float wv = pool[(cc + c) * CRED + o];
#pragma unroll
            for (int pp = 0; pp < 8; pp++)
                racc[pp] += wv * h_sh[c * 64 + pg * 8 + pp];
        }
    }

    // BN + ReLU -> r_sh
    {
        float sc = gamma[o] * rsqrtf(var[o] + 1e-5f);
        float sh = beta[o] - mean[o] * sc;
#pragma unroll
        for (int pp = 0; pp < 8; pp++) {
            float v = racc[pp] * sc + sh;
            r_sh[o][pg * 8 + pp] = fmaxf(v, 0.f);
        }
    }
    __syncthreads();

    // stage 2: wspan into pool (overwrites stage-1 data)
    for (int i = tid; i < SPAN * CRED; i += 256) pool[i] = wspan[i];
    __syncthreads();

    float* wb = g_wgt + (size_t)b * SPAN * PHALF + p0;
    for (int idx = tid; idx < 50 * 64; idx += 256) {
        int s0 = idx >> 6, p = idx & 63;          // s0 in [0,50), uniform per warp
        float v0 = bspan[s0];
        float v1 = bspan[s0 + 50];
        float v2 = bspan[s0 + 100];
        float v3 = bspan[s0 + 150];
        const float* w0 = pool + (s0      ) * CRED;
        const float* w1 = pool + (s0 +  50) * CRED;
        const float* w2 = pool + (s0 + 100) * CRED;
        const float* w3 = pool + (s0 + 150) * CRED;
#pragma unroll
        for (int oo = 0; oo < CRED; oo++) {
            float r = r_sh[oo][p];
            v0 += w0[oo] * r;
            v1 += w1[oo] * r;
            v2 += w2[oo] * r;
            v3 += w3[oo] * r;
        }
        wb[(size_t)(s0      ) * PHALF + p] = v0;
        wb[(size_t)(s0 +  50) * PHALF + p] = v1;
        wb[(size_t)(s0 + 100) * PHALF + p] = v2;
        wb[(size_t)(s0 + 150) * PHALF + p] = v3;
    }
}

// ---------------------------------------------------------------------------
// Kernel 3: involution at full res.
// out[b, g*16+c, y, x] = sum_{kh,kw} wgt[b, g*25+kh*5+kw, y/2, x/2]
//                                    * h[b, g*16+c, (y+kh-2)/2, (x+kw-2)/2]
// Block: (b, g, 16x16 half-pixel tile). Thread = one half-pixel -> 2x2 outputs
// for all 16 group channels. 3x3 half-res neighborhood per channel.
// ---------------------------------------------------------------------------
__global__ __launch_bounds__(256) void inv_k(float* __restrict__ out) {
    __shared__ float hs[GC_][18][19];   // halo'd h tile, ~21.4 KB

    const int b = blockIdx.z;
    const int g = blockIdx.y;
    const int ti = (blockIdx.x >> 2) * 16;
    const int tj = (blockIdx.x & 3) * 16;
    const int tid = threadIdx.x;

    // load h tile (+1 halo each side) with zero pad
    const float* hb = g_h + ((size_t)b * COUT + g * GC_) * PHALF;
    for (int e = tid; e < GC_ * 18 * 18; e += 256) {
        int c   = e / 324;
        int rem = e - c * 324;
        int rr  = rem / 18, cc = rem - rr * 18;
        int gi = ti - 1 + rr, gj = tj - 1 + cc;
        float v = 0.f;
        if ((unsigned)gi < 64u && (unsigned)gj < 64u)
            v = hb[(size_t)c * PHALF + gi * HHALF + gj];
        hs[c][rr][cc] = v;
    }

    const int jl = tid & 15, il = tid >> 4;
    const int pix = (ti + il) * HHALF + (tj + jl);

    // 25 involution weights for this half-pixel (coalesced loads)
    float wk[KK];
    const float* wgp = g_wgt + ((size_t)b * SPAN + g * KK) * PHALF + pix;
#pragma unroll
    for (int k = 0; k < KK; k++) wk[k] = wgp[(size_t)k * PHALF];

    __syncthreads();

    // half-res row/col offset tables: index into 3x3 neighborhood (0..2)
    const int R0[5] = {0, 0, 1, 1, 2};
    const int R1[5] = {0, 1, 1, 2, 2};

    const int y0 = 2 * (ti + il), x0 = 2 * (tj + jl);
    float* ob = out + (((size_t)b * COUT + g * GC_) * 128 + y0) * 128 + x0;

#pragma unroll
    for (int c = 0; c < GC_; c++) {
        float n[3][3];
#pragma unroll
        for (int a = 0; a < 3; a++)
#pragma unroll
            for (int d = 0; d < 3; d++)
                n[a][d] = hs[c][il + a][jl + d];

        float a00 = 0.f, a01 = 0.f, a10 = 0.f, a11 = 0.f;
#pragma unroll
        for (int kh = 0; kh < 5; kh++) {
            const int r0 = R0[kh], r1 = R1[kh];
#pragma unroll
            for (int kw = 0; kw < 5; kw++) {
                const float wv = wk[kh * 5 + kw];
                const int c0 = R0[kw], c1 = R1[kw];
                a00 += wv * n[r0][c0];
                a01 += wv * n[r0][c1];
                a10 += wv * n[r1][c0];
                a11 += wv * n[r1][c1];
            }
        }
        float2 v0 = make_float2(a00, a01);
        float2 v1 = make_float2(a10, a11);
        *reinterpret_cast<float2*>(ob + (size_t)c * 16384)       = v0;
        *reinterpret_cast<float2*>(ob + (size_t)c * 16384 + 128) = v1;
    }
}

// ---------------------------------------------------------------------------
extern "C" void kernel_launch(void* const* d_in, const int* in_sizes, int n_in,
                              void* d_out, int out_size) {
    const float* x      = (const float*)d_in[0];
    const float* w1x1   = (const float*)d_in[1];
    const float* b1x1   = (const float*)d_in[2];
    const float* w_red  = (const float*)d_in[3];
    const float* b_red  = (const float*)d_in[4];
    const float* gamma  = (const float*)d_in[5];
    const float* beta   = (const float*)d_in[6];
    const float* mean   = (const float*)d_in[7];
    const float* var    = (const float*)d_in[8];
    const float* w_span = (const float*)d_in[9];
    const float* b_span = (const float*)d_in[10];
    float* out = (float*)d_out;

    conv1_k<<<dim3(PHALF / 128, 2, B_), 256>>>(x, w1x1, b1x1);
    kgen_k<<<dim3((B_ * PHALF) / 64, 1, 1), 256>>>(w_red, b_red, gamma, beta,
                                                   mean, var, w_span, b_span);
    inv_k<<<dim3(16, GROUPS, B_), 256>>>(out);
}